// round 6
// baseline (speedup 1.0000x reference)
#include <cuda_runtime.h>
#include <math.h>

// Problem dims
#define BB 64
#define SS 1024
#define EE 256
#define HH 1024
#define GG 4096   // 4*H
#define PP 256    // projection size
#define NCTA 128  // persistent grid (< 148 SMs -> all co-resident)

typedef unsigned long long u64;

// ---------------- device scratch (no cudaMalloc allowed) ----------------
__device__ float g_xT[SS * BB * EE];          // x transposed to [t][b][e]      (64 MB)
__device__ float g_WihT[2][EE * GG];          // W_ih^T  [e][g]                 (8 MB)
__device__ float g_WhhT[2][EE * GG];          // W_hh^T  [e][g]                 (8 MB)
__device__ float g_WhrT[2][HH * PP];          // W_hr^T  [u][p]                 (2 MB)
__device__ float g_bias[2][GG];               // b_ih + b_hh
__device__ float g_xg_f[268435456];           // xg fwd [t][b][4H]              (1 GiB)
__device__ float g_xg_b[268435456];           // xg bwd [t][b][4H]              (1 GiB)
__device__ float g_hT[2][PP * BB];            // projected hidden, [dir][p][b]
__device__ float g_c[2][BB * HH];             // cell state [dir][b][u]
__device__ float g_hp[2][BB * HH];            // o*tanh(c)  [dir][b][u]
__device__ unsigned g_bar_count;              // grid barrier arrivals (self-resetting)
__device__ unsigned g_bar_epoch;              // monotonic epoch (wrap-safe compare)

// ---------------- f32x2 packed-FMA helpers (Blackwell FFMA2) ----------------
__device__ __forceinline__ u64 pack2(float x, float y) {
    u64 r; asm("mov.b64 %0, {%1, %2};" : "=l"(r) : "f"(x), "f"(y)); return r;
}
__device__ __forceinline__ void unpack2(u64 v, float& x, float& y) {
    asm("mov.b64 {%0, %1}, %2;" : "=f"(x), "=f"(y) : "l"(v));
}
__device__ __forceinline__ u64 ffma2(u64 a, u64 b, u64 c) {
    u64 d; asm("fma.rn.f32x2 %0, %1, %2, %3;" : "=l"(d) : "l"(a), "l"(b), "l"(c)); return d;
}

// ---------------- activation helpers ----------------
__device__ __forceinline__ float sigf(float x) {
    return 1.0f / (1.0f + __expf(-x));
}
__device__ __forceinline__ float tanh_acc(float x) {
    float ax = fabsf(x);
    float e  = __expf(-2.0f * ax);
    float r  = (1.0f - e) / (1.0f + e);
    return x < 0.0f ? -r : r;
}

// Grid-wide barrier: epoch counting. All NCTA CTAs resident (NCTA < #SMs), so
// spinning is deadlock-free. Release/acquire chain: bar.sync (cta fence) ->
// tid0 __threadfence (gpu) + atomic arrive -> spinner load + __threadfence.
// PTX model cumulativity makes peer writes visible after the barrier.
__device__ __forceinline__ void gsync(unsigned target) {
    __syncthreads();
    if (threadIdx.x == 0) {
        __threadfence();                       // release my CTA's writes
        unsigned old = atomicAdd(&g_bar_count, 1);
        if (old == (unsigned)(gridDim.x - 1)) {
            g_bar_count = 0;
            __threadfence();
            atomicAdd(&g_bar_epoch, 1);
        } else {
            while ((int)(*(volatile unsigned*)&g_bar_epoch - target) < 0) { }
        }
        __threadfence();                       // acquire peers' writes
    }
    __syncthreads();
}

// ---------------- prep: transposes, bias fuse, state zero ----------------
__global__ void prep_kernel(
    const float* __restrict__ x,
    const float* __restrict__ WihF, const float* __restrict__ WhhF,
    const float* __restrict__ bihF, const float* __restrict__ bhhF,
    const float* __restrict__ WhrF,
    const float* __restrict__ WihB, const float* __restrict__ WhhB,
    const float* __restrict__ bihB, const float* __restrict__ bhhB,
    const float* __restrict__ WhrB)
{
    size_t tid = (size_t)blockIdx.x * blockDim.x + threadIdx.x;
    size_t stride = (size_t)gridDim.x * blockDim.x;

    // xT[t][b][e] = x[b][t][e]
    for (size_t o = tid; o < (size_t)SS * BB * EE; o += stride) {
        unsigned e = (unsigned)(o & (EE - 1));
        unsigned b = (unsigned)((o >> 8) & (BB - 1));
        unsigned t = (unsigned)(o >> 14);
        g_xT[o] = x[((size_t)b * SS + t) * EE + e];
    }
    // W_ihT / W_hhT : [e][g] = W[g][e]
    for (size_t o = tid; o < (size_t)2 * EE * GG; o += stride) {
        unsigned d = (unsigned)(o >> 20);
        unsigned r = (unsigned)(o & (EE * GG - 1));
        unsigned g = r & (GG - 1);
        unsigned e = r >> 12;
        const float* Wih = d ? WihB : WihF;
        const float* Whh = d ? WhhB : WhhF;
        g_WihT[d][r] = Wih[(size_t)g * EE + e];
        g_WhhT[d][r] = Whh[(size_t)g * EE + e];
    }
    // W_hrT[u][p] = W_hr[p][u]
    for (size_t o = tid; o < (size_t)2 * HH * PP; o += stride) {
        unsigned d = (unsigned)(o >> 18);
        unsigned r = (unsigned)(o & (HH * PP - 1));
        unsigned p = r & (PP - 1);
        unsigned u = r >> 8;
        const float* Whr = d ? WhrB : WhrF;
        g_WhrT[d][r] = Whr[(size_t)p * HH + u];
    }
    // bias = b_ih + b_hh
    for (size_t o = tid; o < (size_t)2 * GG; o += stride) {
        unsigned d = (unsigned)(o >> 12);
        unsigned g = (unsigned)(o & (GG - 1));
        g_bias[d][g] = d ? (bihB[g] + bhhB[g]) : (bihF[g] + bhhF[g]);
    }
    // zero recurrent state (every replay must restart from h=c=0)
    for (size_t o = tid; o < (size_t)2 * PP * BB; o += stride) ((float*)g_hT)[o] = 0.0f;
    for (size_t o = tid; o < (size_t)2 * BB * HH; o += stride) ((float*)g_c)[o]  = 0.0f;
}

// ---------------- xg = xT @ W_ihT + bias  (M=65536, K=256, N=4096, z=dir) ----
// Tile 64x64, BK=16, 256 threads, 4x4 micro-tile, FFMA2 inner loop.
__global__ __launch_bounds__(256) void xg_gemm_kernel() {
    __shared__ float As[16 * 68];   // [k][m], padded
    __shared__ float Bs[16 * 68];   // [k][n], padded
    const int d = blockIdx.z;
    const float* __restrict__ Wt = g_WihT[d];
    float* __restrict__ outp = d ? g_xg_b : g_xg_f;
    const unsigned m0 = blockIdx.x * 64;
    const unsigned n0 = blockIdx.y * 64;
    const int tid = threadIdx.x;
    const int tn = tid & 15, tm = tid >> 4;
    const int lm = tid >> 2, lk4 = (tid & 3) * 4;       // A loader
    const int lbk = tid >> 4, lbn4 = (tid & 15) * 4;    // B loader

    u64 acc[4][2] = {};   // [mi][n-pair]

    for (int kk = 0; kk < EE; kk += 16) {
        float4 av = *(const float4*)&g_xT[(size_t)(m0 + lm) * EE + kk + lk4];
        float4 bv = *(const float4*)&Wt[(size_t)(kk + lbk) * GG + n0 + lbn4];
        __syncthreads();
        As[(lk4 + 0) * 68 + lm] = av.x;
        As[(lk4 + 1) * 68 + lm] = av.y;
        As[(lk4 + 2) * 68 + lm] = av.z;
        As[(lk4 + 3) * 68 + lm] = av.w;
        Bs[lbk * 68 + lbn4 + 0] = bv.x;
        Bs[lbk * 68 + lbn4 + 1] = bv.y;
        Bs[lbk * 68 + lbn4 + 2] = bv.z;
        Bs[lbk * 68 + lbn4 + 3] = bv.w;
        __syncthreads();
#pragma unroll
        for (int k = 0; k < 16; k++) {
            float4 a = *(const float4*)&As[k * 68 + tm * 4];
            float4 b = *(const float4*)&Bs[k * 68 + tn * 4];
            u64 b01 = pack2(b.x, b.y), b23 = pack2(b.z, b.w);   // natural pairs
            u64 a0 = pack2(a.x, a.x), a1 = pack2(a.y, a.y);
            u64 a2 = pack2(a.z, a.z), a3 = pack2(a.w, a.w);
            acc[0][0] = ffma2(a0, b01, acc[0][0]); acc[0][1] = ffma2(a0, b23, acc[0][1]);
            acc[1][0] = ffma2(a1, b01, acc[1][0]); acc[1][1] = ffma2(a1, b23, acc[1][1]);
            acc[2][0] = ffma2(a2, b01, acc[2][0]); acc[2][1] = ffma2(a2, b23, acc[2][1]);
            acc[3][0] = ffma2(a3, b01, acc[3][0]); acc[3][1] = ffma2(a3, b23, acc[3][1]);
        }
    }
    float4 bias4 = *(const float4*)&g_bias[d][n0 + tn * 4];
#pragma unroll
    for (int mi = 0; mi < 4; mi++) {
        float4 v;
        unpack2(acc[mi][0], v.x, v.y);
        unpack2(acc[mi][1], v.z, v.w);
        v.x += bias4.x; v.y += bias4.y; v.z += bias4.z; v.w += bias4.w;
        *(float4*)&outp[(size_t)(m0 + tm * 4 + mi) * GG + n0 + tn * 4] = v;
    }
}

// ---------------- persistent bidirectional recurrence ----------------
// 128 CTAs x 256 threads, 1024 steps, 2 grid barriers/step.
// Phase A (gates+cell): CTA = (dir, 32-batch block, 32-u block). GEMM 32x128,K=256.
// Phase B (projection): CTA = (dir, 8-batch block, 32-p block). K=1024 split 4 ways.
__global__ __launch_bounds__(256) void lstm_recur_kernel(float* __restrict__ out) {
    __shared__ float sA[8192];   // A: h tile [k][m] (32KB) / B: hp tile [u][bi] (swizzled)
    __shared__ float sB[4096];   // A: W chunk [k][n] then preacts [m][n] / B: reduce buf

    const int tid = threadIdx.x;
    const int cta = blockIdx.x;
    const int d  = cta >> 6;
    const int r6 = cta & 63;
    const int a_b0 = (r6 >> 5) * 32;   // phase A batch origin
    const int a_u0 = (r6 & 31) * 32;   // phase A u origin
    const int b_b0 = (r6 >> 3) * 8;    // phase B batch origin
    const int b_p0 = (r6 & 7) * 32;    // phase B p origin

    const float* __restrict__ xg  = d ? g_xg_b : g_xg_f;
    const float* __restrict__ Whh = g_WhhT[d];
    const float* __restrict__ Whr = g_WhrT[d];
    float* __restrict__ hT = g_hT[d];
    float* __restrict__ cP = g_c[d];
    float* __restrict__ hp = g_hp[d];

    const int tn = tid & 31, tm = tid >> 5;   // phase A compute map (8x32 threads)

    unsigned tgt = 0;
    // Safe: epoch cannot advance until every CTA arrives at its first gsync,
    // which happens only after this read.
    if (tid == 0) tgt = *(volatile unsigned*)&g_bar_epoch;

    for (int t = 0; t < SS; t++) {
        const int tpos = d ? (SS - 1 - t) : t;

        // ---------- Phase A: gate GEMM + cell update ----------
        // load h tile: sA[k*32+m] = hT[k*64 + a_b0 + m]   (k=0..255, m=0..31)
#pragma unroll
        for (int q = 0; q < 32; q++) {
            int idx = tid + q * 256;
            int k = idx >> 5, m = idx & 31;
            sA[idx] = hT[k * 64 + a_b0 + m];
        }

        u64 acc[4][2] = {};   // [mi][n-pair]
        for (int kk = 0; kk < EE; kk += 32) {
            __syncthreads();     // protect sB reuse (and first-iter sA fill)
#pragma unroll
            for (int q = 0; q < 4; q++) {
                int idx  = tid + q * 256;          // float4 index 0..1023
                int k    = idx >> 5;
                int n4   = (idx & 31) * 4;
                int gate = n4 >> 5;
                int ul4  = n4 & 31;
                float4 w = *(const float4*)&Whh[(size_t)(kk + k) * GG + gate * HH + a_u0 + ul4];
                *(float4*)&sB[k * 128 + n4] = w;
            }
            __syncthreads();
#pragma unroll
            for (int k = 0; k < 32; k++) {
                float4 a = *(const float4*)&sA[(kk + k) * 32 + tm * 4];
                float4 b = *(const float4*)&sB[k * 128 + tn * 4];
                u64 b01 = pack2(b.x, b.y), b23 = pack2(b.z, b.w);
                u64 a0 = pack2(a.x, a.x), a1 = pack2(a.y, a.y);
                u64 a2 = pack2(a.z, a.z), a3 = pack2(a.w, a.w);
                acc[0][0] = ffma2(a0, b01, acc[0][0]); acc[0][1] = ffma2(a0, b23, acc[0][1]);
                acc[1][0] = ffma2(a1, b01, acc[1][0]); acc[1][1] = ffma2(a1, b23, acc[1][1]);
                acc[2][0] = ffma2(a2, b01, acc[2][0]); acc[2][1] = ffma2(a2, b23, acc[2][1]);
                acc[3][0] = ffma2(a3, b01, acc[3][0]); acc[3][1] = ffma2(a3, b23, acc[3][1]);
            }
        }
        // stage preacts into sB as [m(32)][n(128)]
        __syncthreads();
#pragma unroll
        for (int mi = 0; mi < 4; mi++) {
            float4 v;
            unpack2(acc[mi][0], v.x, v.y);
            unpack2(acc[mi][1], v.z, v.w);
            *(float4*)&sB[(tm * 4 + mi) * 128 + tn * 4] = v;
        }
        __syncthreads();
        // cell update: 1024 (b,u) pairs, 4 per thread
#pragma unroll
        for (int j = 0; j < 4; j++) {
            int idx = tid + j * 256;
            int bi = idx >> 5, ui = idx & 31;
            const float* xr = xg + ((size_t)tpos * BB + a_b0 + bi) * GG + a_u0 + ui;
            float p_i = sB[bi * 128 +       ui] + xr[0];
            float p_f = sB[bi * 128 +  32 + ui] + xr[HH];
            float p_g = sB[bi * 128 +  64 + ui] + xr[2 * HH];
            float p_o = sB[bi * 128 +  96 + ui] + xr[3 * HH];
            float iv = sigf(p_i), fv = sigf(p_f), gv = tanh_acc(p_g), ov = sigf(p_o);
            size_t ci = (size_t)(a_b0 + bi) * HH + a_u0 + ui;
            float cv = fv * cP[ci] + iv * gv;
            cP[ci] = cv;
            hp[ci] = ov * tanh_acc(cv);
        }
        gsync(++tgt);

        // ---------- Phase B: projection h = hp @ W_hr^T ----------
        // hp tile transposed into sA with XOR swizzle (conflict-free stores):
        // sA[u*8 + (bi ^ ((u>>2)&7))] = hp[(b_b0+bi)*HH + u]
#pragma unroll
        for (int q = 0; q < 32; q++) {
            int idx = tid + q * 256;
            int bi = idx >> 10, u = idx & 1023;
            sA[u * 8 + (bi ^ ((u >> 2) & 7))] = hp[(size_t)(b_b0 + bi) * HH + u];
        }
        __syncthreads();
        {
            int ks = tid >> 6;          // K split 0..3
            int rr = tid & 63;
            int bi = rr >> 3, pi = rr & 7;
            u64 accB[2] = {};
            int ub = ks * 256;
#pragma unroll 4
            for (int u = 0; u < 256; u++) {
                int uu = ub + u;
                float  a = sA[uu * 8 + (bi ^ ((uu >> 2) & 7))];
                float4 w = *(const float4*)&Whr[(size_t)uu * PP + b_p0 + pi * 4];
                u64 ap  = pack2(a, a);
                u64 w01 = pack2(w.x, w.y), w23 = pack2(w.z, w.w);
                accB[0] = ffma2(ap, w01, accB[0]);
                accB[1] = ffma2(ap, w23, accB[1]);
            }
            float4 r4;
            unpack2(accB[0], r4.x, r4.y);
            unpack2(accB[1], r4.z, r4.w);
            *(float4*)&sB[ks * 256 + rr * 4] = r4;
        }
        __syncthreads();
        if (tid < 64) {
            float4 v0 = *(const float4*)&sB[        tid * 4];
            float4 v1 = *(const float4*)&sB[256 +  tid * 4];
            float4 v2 = *(const float4*)&sB[512 +  tid * 4];
            float4 v3 = *(const float4*)&sB[768 +  tid * 4];
            float4 v;
            v.x = v0.x + v1.x + v2.x + v3.x;
            v.y = v0.y + v1.y + v2.y + v3.y;
            v.z = v0.z + v1.z + v2.z + v3.z;
            v.w = v0.w + v1.w + v2.w + v3.w;
            int bi2 = tid >> 3, pi2 = tid & 7;
            int b = b_b0 + bi2, p = b_p0 + pi2 * 4;
            hT[(p + 0) * 64 + b] = v.x;        // transposed h for next step
            hT[(p + 1) * 64 + b] = v.y;
            hT[(p + 2) * 64 + b] = v.z;
            hT[(p + 3) * 64 + b] = v.w;
            *(float4*)&out[((size_t)b * SS + tpos) * 512 + d * PP + p] = v;
        }
        gsync(++tgt);
    }
}

// ---------------- launch ----------------
extern "C" void kernel_launch(void* const* d_in, const int* in_sizes, int n_in,
                              void* d_out, int out_size) {
    (void)in_sizes; (void)n_in; (void)out_size;
    const float* x     = (const float*)d_in[0];
    const float* WihF  = (const float*)d_in[1];
    const float* WhhF  = (const float*)d_in[2];
    const float* bihF  = (const float*)d_in[3];
    const float* bhhF  = (const float*)d_in[4];
    const float* WhrF  = (const float*)d_in[5];
    const float* WihB  = (const float*)d_in[6];
    const float* WhhB  = (const float*)d_in[7];
    const float* bihB  = (const float*)d_in[8];
    const float* bhhB  = (const float*)d_in[9];
    const float* WhrB  = (const float*)d_in[10];
    float* out = (float*)d_out;

    prep_kernel<<<2048, 256>>>(x, WihF, WhhF, bihF, bhhF, WhrF,
                                  WihB, WhhB, bihB, bhhB, WhrB);
    dim3 g(1024, 64, 2);     // M/64, N/64, dir
    xg_gemm_kernel<<<g, 256>>>();
    lstm_recur_kernel<<<NCTA, 256>>>(out);
}

// round 14
// speedup vs baseline: 1.4129x; 1.4129x over previous
#include <cuda_runtime.h>
#include <math.h>

// Problem dims
#define BB 64
#define SS 1024
#define EE 256
#define HH 1024
#define GG 4096   // 4*H
#define PP 256    // projection size
#define NCTA 128  // persistent grid, 1 CTA/SM (smem-bound), all co-resident

typedef unsigned long long u64;

// ---------------- device scratch (no cudaMalloc allowed) ----------------
__device__ float g_xT[SS * BB * EE];          // x transposed to [t][b][e]
__device__ float g_WihT[2][EE * GG];          // W_ih^T  [e][g]
__device__ float g_WhhT[2][EE * GG];          // W_hh^T  [e][g]
__device__ float g_WhrT[2][HH * PP];          // W_hr^T  [u][p]
__device__ float g_bias[2][GG];               // b_ih + b_hh
__device__ float g_xg_f[268435456];           // xg fwd [t][ublk][gate][u15][b]
__device__ float g_xg_b[268435456];           // xg bwd same layout
__device__ float g_hT[2][PP * BB];            // projected hidden, [dir][p][b]
__device__ float g_hpT[2][HH * BB];           // o*tanh(c), [dir][u][b]
__device__ unsigned g_bar_count;              // grid barrier arrivals
__device__ unsigned g_bar_epoch;              // monotonic epoch

// ---------------- f32x2 packed-FMA helpers (Blackwell FFMA2) ----------------
__device__ __forceinline__ u64 pack2(float x, float y) {
    u64 r; asm("mov.b64 %0, {%1, %2};" : "=l"(r) : "f"(x), "f"(y)); return r;
}
__device__ __forceinline__ void unpack2(u64 v, float& x, float& y) {
    asm("mov.b64 {%0, %1}, %2;" : "=f"(x), "=f"(y) : "l"(v));
}
__device__ __forceinline__ u64 ffma2(u64 a, u64 b, u64 c) {
    u64 d; asm("fma.rn.f32x2 %0, %1, %2, %3;" : "=l"(d) : "l"(a), "l"(b), "l"(c)); return d;
}

// ---------------- activation helpers ----------------
__device__ __forceinline__ float sigf(float x) {
    return 1.0f / (1.0f + __expf(-x));
}
__device__ __forceinline__ float tanh_acc(float x) {
    float ax = fabsf(x);
    float e  = __expf(-2.0f * ax);
    float r  = (1.0f - e) / (1.0f + e);
    return x < 0.0f ? -r : r;
}

// Grid-wide barrier (epoch counting; all CTAs resident -> deadlock-free).
__device__ __forceinline__ void gsync(unsigned target) {
    __syncthreads();
    if (threadIdx.x == 0) {
        __threadfence();                       // release my CTA's writes
        unsigned old = atomicAdd(&g_bar_count, 1);
        if (old == (unsigned)(gridDim.x - 1)) {
            g_bar_count = 0;
            __threadfence();
            atomicAdd(&g_bar_epoch, 1);
        } else {
            while ((int)(*(volatile unsigned*)&g_bar_epoch - target) < 0) { }
        }
        __threadfence();                       // acquire peers' writes
    }
    __syncthreads();
}

// ---------------- prep: transposes, bias fuse, state zero ----------------
__global__ void prep_kernel(
    const float* __restrict__ x,
    const float* __restrict__ WihF, const float* __restrict__ WhhF,
    const float* __restrict__ bihF, const float* __restrict__ bhhF,
    const float* __restrict__ WhrF,
    const float* __restrict__ WihB, const float* __restrict__ WhhB,
    const float* __restrict__ bihB, const float* __restrict__ bhhB,
    const float* __restrict__ WhrB)
{
    size_t tid = (size_t)blockIdx.x * blockDim.x + threadIdx.x;
    size_t stride = (size_t)gridDim.x * blockDim.x;

    // xT[t][b][e] = x[b][t][e]
    for (size_t o = tid; o < (size_t)SS * BB * EE; o += stride) {
        unsigned e = (unsigned)(o & (EE - 1));
        unsigned b = (unsigned)((o >> 8) & (BB - 1));
        unsigned t = (unsigned)(o >> 14);
        g_xT[o] = x[((size_t)b * SS + t) * EE + e];
    }
    // W_ihT / W_hhT : [e][g] = W[g][e]
    for (size_t o = tid; o < (size_t)2 * EE * GG; o += stride) {
        unsigned d = (unsigned)(o >> 20);
        unsigned r = (unsigned)(o & (EE * GG - 1));
        unsigned g = r & (GG - 1);
        unsigned e = r >> 12;
        const float* Wih = d ? WihB : WihF;
        const float* Whh = d ? WhhB : WhhF;
        g_WihT[d][r] = Wih[(size_t)g * EE + e];
        g_WhhT[d][r] = Whh[(size_t)g * EE + e];
    }
    // W_hrT[u][p] = W_hr[p][u]
    for (size_t o = tid; o < (size_t)2 * HH * PP; o += stride) {
        unsigned d = (unsigned)(o >> 18);
        unsigned r = (unsigned)(o & (HH * PP - 1));
        unsigned p = r & (PP - 1);
        unsigned u = r >> 8;
        const float* Whr = d ? WhrB : WhrF;
        g_WhrT[d][r] = Whr[(size_t)p * HH + u];
    }
    // bias = b_ih + b_hh
    for (size_t o = tid; o < (size_t)2 * GG; o += stride) {
        unsigned d = (unsigned)(o >> 12);
        unsigned g = (unsigned)(o & (GG - 1));
        g_bias[d][g] = d ? (bihB[g] + bhhB[g]) : (bihF[g] + bhhF[g]);
    }
    // zero h (every replay must restart from h=0; c is smem-resident, zeroed in-kernel)
    for (size_t o = tid; o < (size_t)2 * PP * BB; o += stride) ((float*)g_hT)[o] = 0.0f;
}

// ---------------- xg = xT @ W_ihT + bias  (M=65536, K=256, N=4096, z=dir) ----
// Tile 64x64 (one tile == one t), BK=16, 256 threads, 4x4 micro, FFMA2.
// Epilogue restages through smem to emit the recurrence-friendly layout
//   xg[t][u>>4][gate][u&15][b]  with coalesced 256B row stores.
__global__ __launch_bounds__(256) void xg_gemm_kernel() {
    __shared__ float As[16 * 68];   // [k][m], padded
    __shared__ float Bs[16 * 68];   // [k][n], padded
    __shared__ float sT[64 * 68];   // [n][m] staging, padded
    const int d = blockIdx.z;
    const float* __restrict__ Wt = g_WihT[d];
    float* __restrict__ outp = d ? g_xg_b : g_xg_f;
    const unsigned m0 = blockIdx.x * 64;       // tile covers one t (m = t*64 + b)
    const unsigned n0 = blockIdx.y * 64;       // within one gate (1024 % 64 == 0)
    const int tid = threadIdx.x;
    const int tn = tid & 15, tm = tid >> 4;
    const int lm = tid >> 2, lk4 = (tid & 3) * 4;       // A loader
    const int lbk = tid >> 4, lbn4 = (tid & 15) * 4;    // B loader

    u64 acc[4][2] = {};   // [mi][n-pair]

    for (int kk = 0; kk < EE; kk += 16) {
        float4 av = *(const float4*)&g_xT[(size_t)(m0 + lm) * EE + kk + lk4];
        float4 bv = *(const float4*)&Wt[(size_t)(kk + lbk) * GG + n0 + lbn4];
        __syncthreads();
        As[(lk4 + 0) * 68 + lm] = av.x;
        As[(lk4 + 1) * 68 + lm] = av.y;
        As[(lk4 + 2) * 68 + lm] = av.z;
        As[(lk4 + 3) * 68 + lm] = av.w;
        Bs[lbk * 68 + lbn4 + 0] = bv.x;
        Bs[lbk * 68 + lbn4 + 1] = bv.y;
        Bs[lbk * 68 + lbn4 + 2] = bv.z;
        Bs[lbk * 68 + lbn4 + 3] = bv.w;
        __syncthreads();
#pragma unroll
        for (int k = 0; k < 16; k++) {
            float4 a = *(const float4*)&As[k * 68 + tm * 4];
            float4 b = *(const float4*)&Bs[k * 68 + tn * 4];
            u64 b01 = pack2(b.x, b.y), b23 = pack2(b.z, b.w);
            u64 a0 = pack2(a.x, a.x), a1 = pack2(a.y, a.y);
            u64 a2 = pack2(a.z, a.z), a3 = pack2(a.w, a.w);
            acc[0][0] = ffma2(a0, b01, acc[0][0]); acc[0][1] = ffma2(a0, b23, acc[0][1]);
            acc[1][0] = ffma2(a1, b01, acc[1][0]); acc[1][1] = ffma2(a1, b23, acc[1][1]);
            acc[2][0] = ffma2(a2, b01, acc[2][0]); acc[2][1] = ffma2(a2, b23, acc[2][1]);
            acc[3][0] = ffma2(a3, b01, acc[3][0]); acc[3][1] = ffma2(a3, b23, acc[3][1]);
        }
    }
    // stage [n][m] then write new layout with coalesced rows
#pragma unroll
    for (int mi = 0; mi < 4; mi++) {
        float4 v;
        unpack2(acc[mi][0], v.x, v.y);
        unpack2(acc[mi][1], v.z, v.w);
        sT[(tn * 4 + 0) * 68 + tm * 4 + mi] = v.x;
        sT[(tn * 4 + 1) * 68 + tm * 4 + mi] = v.y;
        sT[(tn * 4 + 2) * 68 + tm * 4 + mi] = v.z;
        sT[(tn * 4 + 3) * 68 + tm * 4 + mi] = v.w;
    }
    __syncthreads();
    const int gate = n0 >> 10;
    const int ub   = n0 & 1023;
    float* op = outp + (size_t)m0 * 4096;   // = t * 262144
#pragma unroll
    for (int q = 0; q < 4; q++) {
        int idx4 = tid + q * 256;
        int nl = idx4 >> 4;
        int m4 = (idx4 & 15) * 4;
        int u  = ub + nl;
        float bz = g_bias[d][n0 + nl];
        float4 v = *(const float4*)&sT[nl * 68 + m4];
        v.x += bz; v.y += bz; v.z += bz; v.w += bz;
        *(float4*)&op[(size_t)(u >> 4) * 4096 + gate * 1024 + (u & 15) * 64 + m4] = v;
    }
}

// ---------------- persistent recurrence, SMEM-resident weights ----------------
// 128 CTAs x 256 thr, 212.5 KB dynamic smem, 1 CTA/SM.
// Phase A: CTA=(dir, u-block 16): gates 64b x (4 gates x 16 u), K=256; Whh slice
//          (64 KB) and cell state c (4 KB) SMEM-resident.
// Phase B: CTA=(dir, b-block 16, p-block 16): h = hp @ Whr^T, K=1024 split x4;
//          Whr slice (64 KB) SMEM-resident.
// xg prefetch for step t+1 is software-pipelined into phase B of step t.
#define SM_WHH 0                          // 16384 floats
#define SM_WHR 16384                      // 16384
#define SM_H   32768                      // 16384 (phase-A h tile / phase-B hp tile)
#define SM_PRE 49152                      // 64*65 = 4160 (preacts / reduce buf)
#define SM_C   53312                      // 64*17 = 1088 (cell state, padded)
#define SM_TOTF 54400                     // total floats -> 217600 bytes

__global__ __launch_bounds__(256) void lstm_recur2(float* __restrict__ out) {
    extern __shared__ float smem[];
    float* sWhh = smem + SM_WHH;
    float* sWhr = smem + SM_WHR;
    float* sH   = smem + SM_H;
    float* sPre = smem + SM_PRE;
    float* sC   = smem + SM_C;

    const int tid = threadIdx.x;
    const int cta = blockIdx.x;
    const int d   = cta >> 6;
    const int r6  = cta & 63;
    const int u0  = r6 * 16;              // phase A u-block
    const int bB0 = (r6 >> 4) * 16;       // phase B batch block
    const int p0  = (r6 & 15) * 16;       // phase B p block

    const float* __restrict__ xg   = d ? g_xg_b : g_xg_f;
    const float* __restrict__ WhhT = g_WhhT[d];
    const float* __restrict__ WhrT = g_WhrT[d];
    float* __restrict__ hT  = g_hT[d];
    float* __restrict__ hpT = g_hpT[d];

    // ---- one-time resident fills ----
#pragma unroll
    for (int q = 0; q < 16; q++) {        // sWhh[k*64 + gate*16 + ul]
        int idx4 = tid + q * 256;
        int k  = idx4 >> 4;
        int n4 = (idx4 & 15) * 4;
        int gate = n4 >> 4;
        int ul = n4 & 15;
        *(float4*)&sWhh[k * 64 + n4] =
            *(const float4*)&WhhT[(size_t)k * GG + gate * HH + u0 + ul];
    }
#pragma unroll
    for (int q = 0; q < 16; q++) {        // sWhr[u*16 + pl]
        int idx4 = tid + q * 256;
        int u = idx4 >> 2;
        int pl4 = (idx4 & 3) * 4;
        *(float4*)&sWhr[u * 16 + pl4] = *(const float4*)&WhrT[(size_t)u * PP + p0 + pl4];
    }
    for (int i = tid; i < 64 * 17; i += 256) sC[i] = 0.0f;
    __syncthreads();

    // phase-A compute map: warp w: m-half (w&1)*32, n-quarter (w>>1)*16
    const int w = tid >> 5, l = tid & 31;
    const int am = (w & 1) * 32 + (l >> 2) * 4;   // 4-m base
    const int bn = (w >> 1) * 16 + (l & 3) * 4;   // 4-n base
    // cell map: (u = tid>>4, b = (tid&15)*4 + j)
    const int cu  = tid >> 4;
    const int cb4 = (tid & 15) * 4;
    // phase-B map
    const int ks = tid >> 6;              // K split 0..3
    const int rr = tid & 63;
    const int bl = rr & 15, pq = rr >> 4;

    unsigned tgt = 0;
    // Safe: epoch can't advance until every CTA reaches its first gsync.
    if (tid == 0) tgt = *(volatile unsigned*)&g_bar_epoch;

    // ---- peeled xg prefetch for t=0 (pipelined thereafter) ----
    float4 xq0, xq1, xq2, xq3;
    {
        const int tp0 = d ? (SS - 1) : 0;
        const float* xb = xg + (size_t)tp0 * 262144 + (size_t)r6 * 4096;
        xq0 = *(const float4*)&xb[0 * 1024 + tid * 4];
        xq1 = *(const float4*)&xb[1 * 1024 + tid * 4];
        xq2 = *(const float4*)&xb[2 * 1024 + tid * 4];
        xq3 = *(const float4*)&xb[3 * 1024 + tid * 4];
    }

    for (int t = 0; t < SS; t++) {
        const int tpos = d ? (SS - 1 - t) : t;

        // ---------- Phase A ----------
        // h tile: contiguous 64 KB copy hT -> sH ([k][64 b])
#pragma unroll
        for (int q = 0; q < 16; q++) {
            int idx4 = tid + q * 256;
            *(float4*)&sH[idx4 * 4] = *(const float4*)&hT[idx4 * 4];
        }
        __syncthreads();

        // gate GEMM: 64b x 64n, K=256, all operands in SMEM, no syncs
        u64 acc[4][2] = {};
#pragma unroll 8
        for (int k = 0; k < 256; k++) {
            float4 a = *(const float4*)&sH[k * 64 + am];
            ulonglong2 b = *(const ulonglong2*)&sWhh[k * 64 + bn];
            u64 a0 = pack2(a.x, a.x), a1 = pack2(a.y, a.y);
            u64 a2 = pack2(a.z, a.z), a3 = pack2(a.w, a.w);
            acc[0][0] = ffma2(a0, b.x, acc[0][0]); acc[0][1] = ffma2(a0, b.y, acc[0][1]);
            acc[1][0] = ffma2(a1, b.x, acc[1][0]); acc[1][1] = ffma2(a1, b.y, acc[1][1]);
            acc[2][0] = ffma2(a2, b.x, acc[2][0]); acc[2][1] = ffma2(a2, b.y, acc[2][1]);
            acc[3][0] = ffma2(a3, b.x, acc[3][0]); acc[3][1] = ffma2(a3, b.y, acc[3][1]);
        }
        // stage preacts sPre[b*65 + n]  (n = gate*16 + ul)
#pragma unroll
        for (int mi = 0; mi < 4; mi++) {
            float4 v;
            unpack2(acc[mi][0], v.x, v.y);
            unpack2(acc[mi][1], v.z, v.w);
            sPre[(am + mi) * 65 + bn + 0] = v.x;
            sPre[(am + mi) * 65 + bn + 1] = v.y;
            sPre[(am + mi) * 65 + bn + 2] = v.z;
            sPre[(am + mi) * 65 + bn + 3] = v.w;
        }
        __syncthreads();

        // cell update: 4 b-contiguous cells per thread, c SMEM-resident
        {
            float hout[4];
            const float* xi  = (const float*)&xq0;
            const float* xf  = (const float*)&xq1;
            const float* xgv = (const float*)&xq2;
            const float* xo  = (const float*)&xq3;
#pragma unroll
            for (int j = 0; j < 4; j++) {
                int b = cb4 + j;
                float p_i = sPre[b * 65 +      cu] + xi[j];
                float p_f = sPre[b * 65 + 16 + cu] + xf[j];
                float p_g = sPre[b * 65 + 32 + cu] + xgv[j];
                float p_o = sPre[b * 65 + 48 + cu] + xo[j];
                float iv = sigf(p_i), fv = sigf(p_f);
                float gv = tanh_acc(p_g), ov = sigf(p_o);
                float cv = fv * sC[b * 17 + cu] + iv * gv;
                sC[b * 17 + cu] = cv;
                hout[j] = ov * tanh_acc(cv);
            }
            *(float4*)&hpT[(size_t)(u0 + cu) * 64 + cb4] = *(float4*)hout;
        }
        gsync(++tgt);

        // ---------- Phase B: h = hp @ Whr^T ----------
        // hp tile: sH[u*16 + b] from hpT[u*64 + bB0 + b]
#pragma unroll
        for (int q = 0; q < 16; q++) {
            int idx4 = tid + q * 256;
            int u = idx4 >> 2;
            int b4 = (idx4 & 3) * 4;
            *(float4*)&sH[u * 16 + b4] = *(const float4*)&hpT[(size_t)u * 64 + bB0 + b4];
        }
        __syncthreads();

        // pipelined xg prefetch for step t+1 (xg is read-only; independent of
        // all barriers — issued here so the 256-iter FFMA loop + trailing
        // gsync hide the DRAM latency)
        if (t + 1 < SS) {
            const int tnext = d ? (SS - 2 - t) : (t + 1);
            const float* xb = xg + (size_t)tnext * 262144 + (size_t)r6 * 4096;
            xq0 = *(const float4*)&xb[0 * 1024 + tid * 4];
            xq1 = *(const float4*)&xb[1 * 1024 + tid * 4];
            xq2 = *(const float4*)&xb[2 * 1024 + tid * 4];
            xq3 = *(const float4*)&xb[3 * 1024 + tid * 4];
        }

        {
            u64 accB0 = 0, accB1 = 0;
            const int kbase = ks * 256;
#pragma unroll 4
            for (int k = 0; k < 256; k++) {
                float a = sH[(kbase + k) * 16 + bl];
                ulonglong2 wv = *(const ulonglong2*)&sWhr[(kbase + k) * 16 + pq * 4];
                u64 ap = pack2(a, a);
                accB0 = ffma2(ap, wv.x, accB0);
                accB1 = ffma2(ap, wv.y, accB1);
            }
            float4 r4;
            unpack2(accB0, r4.x, r4.y);
            unpack2(accB1, r4.z, r4.w);
            *(float4*)&sPre[ks * 256 + rr * 4] = r4;
        }
        __syncthreads();
        if (tid < 64) {
            float4 v0 = *(const float4*)&sPre[      tid * 4];
            float4 v1 = *(const float4*)&sPre[256 + tid * 4];
            float4 v2 = *(const float4*)&sPre[512 + tid * 4];
            float4 v3 = *(const float4*)&sPre[768 + tid * 4];
            float4 v;
            v.x = v0.x + v1.x + v2.x + v3.x;
            v.y = v0.y + v1.y + v2.y + v3.y;
            v.z = v0.z + v1.z + v2.z + v3.z;
            v.w = v0.w + v1.w + v2.w + v3.w;
            int b = bB0 + (tid & 15);
            int p = p0 + (tid >> 4) * 4;
            hT[(p + 0) * 64 + b] = v.x;
            hT[(p + 1) * 64 + b] = v.y;
            hT[(p + 2) * 64 + b] = v.z;
            hT[(p + 3) * 64 + b] = v.w;
            *(float4*)&out[((size_t)b * SS + tpos) * 512 + d * PP + p] = v;
        }
        gsync(++tgt);
    }
}

// ---------------- launch ----------------
extern "C" void kernel_launch(void* const* d_in, const int* in_sizes, int n_in,
                              void* d_out, int out_size) {
    (void)in_sizes; (void)n_in; (void)out_size;
    const float* x     = (const float*)d_in[0];
    const float* WihF  = (const float*)d_in[1];
    const float* WhhF  = (const float*)d_in[2];
    const float* bihF  = (const float*)d_in[3];
    const float* bhhF  = (const float*)d_in[4];
    const float* WhrF  = (const float*)d_in[5];
    const float* WihB  = (const float*)d_in[6];
    const float* WhhB  = (const float*)d_in[7];
    const float* bihB  = (const float*)d_in[8];
    const float* bhhB  = (const float*)d_in[9];
    const float* WhrB  = (const float*)d_in[10];
    float* out = (float*)d_out;

    // Non-stream API: executes immediately (first call happens in the
    // uncaptured correctness invocation), idempotent thereafter.
    cudaFuncSetAttribute(lstm_recur2,
                         cudaFuncAttributeMaxDynamicSharedMemorySize,
                         SM_TOTF * (int)sizeof(float));

    prep_kernel<<<2048, 256>>>(x, WihF, WhhF, bihF, bhhF, WhrF,
                                  WihB, WhhB, bihB, bhhB, WhrB);
    dim3 g(1024, 64, 2);     // (t, n/64, dir)
    xg_gemm_kernel<<<g, 256>>>();
    lstm_recur2<<<NCTA, 256, SM_TOTF * (int)sizeof(float)>>>(out);
}